// round 13
// baseline (speedup 1.0000x reference)
#include <cuda_runtime.h>
#include <cuda_fp8.h>
#include <cuda_fp16.h>
#include <math_constants.h>
#include <cstdint>

#define SQ 4096
#define HD 64
#define NH 16
#define BM 128
#define BN 128
#define NT (SQ / BN)
#define KSTR8 80           // K smem row stride in BYTES (conflict-free LDS.32 pattern)
#define VSTR 136           // V smem row stride in halves (272B: ldmatrix conflict-free)
#define KB8 (BN * KSTR8)         // 10240
#define VBYTES (HD * VSTR * 2)   // 17408
#define SMEM_TOT (3 * KB8 + 3 * VBYTES)  // 82944 (x2 CTAs = 166KB)

// Q/K as raw e4m3 codes (1 byte); V codes held exactly in fp16 (PV stays fp16 MMA)
__device__ uint8_t g_q8b[NH * SQ * HD];
__device__ uint8_t g_k8b[NH * SQ * HD];
__device__ __half  g_v8t[NH * HD * SQ];   // transposed [h][d][s]

// ---------- helpers ----------
__device__ __forceinline__ uint32_t s2u(const void* p) {
    uint32_t a;
    asm("{ .reg .u64 t; cvta.to.shared.u64 t, %1; cvt.u32.u64 %0, t; }"
        : "=r"(a) : "l"(p));
    return a;
}
__device__ __forceinline__ void cpa16(uint32_t dst, const void* src) {
    asm volatile("cp.async.cg.shared.global [%0], [%1], 16;" :: "r"(dst), "l"(src));
}
#define CPC() asm volatile("cp.async.commit_group;" ::: "memory")
#define CPW1() asm volatile("cp.async.wait_group 1;" ::: "memory")

// fp16 m16n8k16 (PV)
__device__ __forceinline__ void mma16816(float* c, const uint32_t* a,
                                         uint32_t b0, uint32_t b1) {
    asm volatile(
        "mma.sync.aligned.m16n8k16.row.col.f32.f16.f16.f32 "
        "{%0,%1,%2,%3}, {%4,%5,%6,%7}, {%8,%9}, {%0,%1,%2,%3};"
        : "+f"(c[0]), "+f"(c[1]), "+f"(c[2]), "+f"(c[3])
        : "r"(a[0]), "r"(a[1]), "r"(a[2]), "r"(a[3]), "r"(b0), "r"(b1));
}
// fp8 m16n8k32 (QK): A/B are raw e4m3 codes, fp32 accumulate (exact products)
__device__ __forceinline__ void mma8(float* c, const uint32_t* a,
                                     uint32_t b0, uint32_t b1) {
    asm volatile(
        "mma.sync.aligned.m16n8k32.row.col.f32.e4m3.e4m3.f32 "
        "{%0,%1,%2,%3}, {%4,%5,%6,%7}, {%8,%9}, {%0,%1,%2,%3};"
        : "+f"(c[0]), "+f"(c[1]), "+f"(c[2]), "+f"(c[3])
        : "r"(a[0]), "r"(a[1]), "r"(a[2]), "r"(a[3]), "r"(b0), "r"(b1));
}
__device__ __forceinline__ void ldm4(uint32_t* r, uint32_t addr) {
    asm volatile("ldmatrix.sync.aligned.m8n8.x4.shared.b16 {%0,%1,%2,%3}, [%4];"
                 : "=r"(r[0]), "=r"(r[1]), "=r"(r[2]), "=r"(r[3]) : "r"(addr));
}

// MUFU exp2 — same accuracy class (~2.4e-7) as the __expf that passed in R0
__device__ __forceinline__ float exp2p(float t) {
    float r;
    asm("ex2.approx.f32 %0, %1;" : "=f"(r) : "f"(t));
    return r;
}

// pair of floats -> e4m3 codes (satfinite RN-even) packed in 16 bits
__device__ __forceinline__ uint16_t c8pair(float x, float y) {
    return (uint16_t)__nv_cvt_float2_to_fp8x2(make_float2(x, y),
                                              __NV_SATFINITE, __NV_E4M3);
}
// pair of floats -> e4m3 grid -> fp16 pair (exact) for the PV fp16 path
__device__ __forceinline__ uint32_t q8pair(float x, float y) {
    __nv_fp8x2_storage_t b2 = __nv_cvt_float2_to_fp8x2(make_float2(x, y),
                                                       __NV_SATFINITE, __NV_E4M3);
    __half2_raw h2 = __nv_cvt_fp8x2_to_halfraw2(b2, __NV_E4M3);
    return *reinterpret_cast<const uint32_t*>(&h2);
}

// ---------- preprocessing: fp32 -> e4m3 code bytes ----------
// grid.z selects (input, scale): 0 -> q, 1 -> k
__global__ void quant8(const float4* __restrict__ qin, const float4* __restrict__ kin,
                       uint32_t* __restrict__ qout, uint32_t* __restrict__ kout,
                       const float* __restrict__ sq_p, const float* __restrict__ sk_p,
                       int n4) {
    int i = blockIdx.x * blockDim.x + threadIdx.x;
    if (i >= n4) return;
    const float4* in = blockIdx.z ? kin : qin;
    uint32_t* outp = blockIdx.z ? kout : qout;
    float inv = 1.0f / (blockIdx.z ? *sk_p : *sq_p);
    float4 v = in[i];
    uint32_t lo = c8pair(v.x * inv, v.y * inv);
    uint32_t hi = c8pair(v.z * inv, v.w * inv);
    outp[i] = lo | (hi << 16);
}

__global__ void vtrans(const float* __restrict__ v, const float* __restrict__ sp) {
    __shared__ __half t[64][66];
    int h = blockIdx.y, st = blockIdx.x * 64;
    float inv = 1.0f / *sp;
    int tid = threadIdx.x;
#pragma unroll
    for (int e = 0; e < 16; e++) {
        int lin = tid + e * 256;
        int sr = lin >> 6, d = lin & 63;
        uint32_t pr = q8pair(v[((size_t)h * SQ + st + sr) * HD + d] * inv, 0.0f);
        t[sr][d] = *reinterpret_cast<const __half*>(&pr);
    }
    __syncthreads();
#pragma unroll
    for (int e = 0; e < 16; e++) {
        int lin = tid + e * 256;
        int d = lin >> 6, sc = lin & 63;
        g_v8t[((size_t)h * HD + d) * SQ + st + sc] = t[sc][d];
    }
}

// ---- shared macros ----
// K tile prefetch: 128 rows x 64 code bytes, smem stride 80
#define PFK(t, b) do {                                                        \
        const uint8_t* src = Kp8 + (size_t)(t) * BN * HD;                     \
        uint32_t db = sb + (b) * KB8;                                         \
        _Pragma("unroll")                                                     \
        for (int i_ = 0; i_ < 2; i_++) {                                      \
            int idx = tid + i_ * 256; int row = idx >> 2, seg = idx & 3;      \
            cpa16(db + row * KSTR8 + seg * 16, src + row * HD + seg * 16);    \
        } } while (0)
#define PFV(t, b) do {                                                        \
        uint32_t db = sb + 3 * KB8 + (b) * VBYTES;                            \
        _Pragma("unroll")                                                     \
        for (int i_ = 0; i_ < 4; i_++) {                                      \
            int idx = tid + i_ * 256; int d = idx >> 4, seg = idx & 15;       \
            cpa16(db + d * (VSTR * 2) + seg * 16,                             \
                  Vp + (size_t)d * SQ + (t) * BN + seg * 8);                  \
        } } while (0)
// QK score block: 16 rows x 32 keys via fp8 m16n8k32 (2 MMAs per 8-key n-tile)
#define QKBLK(sc, kptr, q) do {                                               \
        _Pragma("unroll")                                                     \
        for (int jj_ = 0; jj_ < 4; jj_++) {                                   \
            sc[jj_][0] = sc[jj_][1] = sc[jj_][2] = sc[jj_][3] = 0.0f;         \
            const char* ba_ = (kptr) + ((q) * 32 + jj_ * 8) * KSTR8 + kq8_lane;\
            uint32_t b0_ = *(const uint32_t*)(ba_);                           \
            uint32_t b1_ = *(const uint32_t*)(ba_ + 16);                      \
            uint32_t b2_ = *(const uint32_t*)(ba_ + 32);                      \
            uint32_t b3_ = *(const uint32_t*)(ba_ + 48);                      \
            mma8(sc[jj_], qa0, b0_, b1_);                                     \
            mma8(sc[jj_], qa1, b2_, b3_);                                     \
        } } while (0)
// pass-1 per-q work: accumulate sumexp from a score block
#define SUMBLK(sc) do {                                                       \
        float a0_ = 0.0f, a1_ = 0.0f;                                         \
        _Pragma("unroll")                                                     \
        for (int jj_ = 0; jj_ < 4; jj_++) {                                   \
            a0_ += exp2p(sc[jj_][0] * qs2) + exp2p(sc[jj_][1] * qs2);         \
            a1_ += exp2p(sc[jj_][2] * qs2) + exp2p(sc[jj_][3] * qs2);         \
        }                                                                     \
        l0 += a0_;                                                            \
        l1 += a1_;                                                            \
    } while (0)
// pass-2 per-q work: quantize probs (fp16 frags) + PV fp16 MMAs, V ldm early
#define PVQ(sc, q) do {                                                       \
        uint32_t gA_[4], gB_[4];                                              \
        uint32_t avb_ = vbuf + v_lane + (uint32_t)((q) * 64);                 \
        ldm4(gA_, avb_);                                                      \
        uint32_t pa[2][4];                                                    \
        _Pragma("unroll")                                                     \
        for (int c_ = 0; c_ < 2; c_++) {                                      \
            _Pragma("unroll")                                                 \
            for (int hf_ = 0; hf_ < 2; hf_++) {                               \
                const float* s4_ = sc[2 * c_ + hf_];                          \
                float e00_ = exp2p(fmaf(s4_[0], qs2, C0));                    \
                float e01_ = exp2p(fmaf(s4_[1], qs2, C0));                    \
                float e10_ = exp2p(fmaf(s4_[2], qs2, C1));                    \
                float e11_ = exp2p(fmaf(s4_[3], qs2, C1));                    \
                pa[c_][2 * hf_ + 0] = q8pair(e00_, e01_);                     \
                pa[c_][2 * hf_ + 1] = q8pair(e10_, e11_);                     \
            }                                                                 \
        }                                                                     \
        _Pragma("unroll")                                                     \
        for (int dt_ = 0; dt_ < 8; dt_++) {                                   \
            uint32_t* gc_ = (dt_ & 1) ? gB_ : gA_;                            \
            uint32_t* gn_ = (dt_ & 1) ? gA_ : gB_;                            \
            if (dt_ < 7)                                                      \
                ldm4(gn_, avb_ + (uint32_t)((dt_ + 1) * 8) * (VSTR * 2));     \
            mma16816(oacc[dt_], pa[0], gc_[0], gc_[1]);                       \
            mma16816(oacc[dt_], pa[1], gc_[2], gc_[3]);                       \
        } } while (0)

// ---------- fused attention: pass 1 (sumexp) + pass 2 (quantized probs + PV) ----------
__global__ __launch_bounds__(256, 2) void attn_kernel(
    const float* __restrict__ sq_p, const float* __restrict__ sk_p,
    const float* __restrict__ sv_p, const float* __restrict__ dsc_p,
    const float* __restrict__ osc_p, float* __restrict__ out) {
    extern __shared__ char smc[];
    const uint32_t sb = s2u(smc);
    const int tid = threadIdx.x;
    const int w = tid >> 5, l = tid & 31;
    const int qr = l >> 2, qc = l & 3;
    const int h = blockIdx.y, s0 = blockIdx.x * BM;
    const int wodd = w & 1;   // odd warps sweep q-blocks in reverse (phase stagger)

    const float sqv = __ldg(sq_p), skv = __ldg(sk_p), svv = __ldg(sv_p);
    const float dsc = __ldg(dsc_p), osc = __ldg(osc_p);
    const float qs2 = sqv * skv * 0.125f * 1.4426950408889634f;

    // lane offsets: fp8 B-operand (n = l>>2 key, k-bytes (l&3)*4); fp16 V ldmatrix
    const int kq8_lane = (l >> 2) * KSTR8 + (l & 3) * 4;
    const uint32_t v_lane = (uint32_t)(l & 7) * (VSTR * 2) + (uint32_t)(l >> 3) * 16;

    const uint8_t* Qp8 = g_q8b + ((size_t)h * SQ + s0 + w * 16) * HD;
    const uint8_t* Kp8 = g_k8b + (size_t)h * SQ * HD;
    const __half* Vp = g_v8t + (size_t)h * HD * SQ;

    // Q fp8 A-fragments: 16 rows x 64 d per warp = 2 k32-chunks x 4 regs
    uint32_t qa0[4], qa1[4];
    {
        const int tg4 = (l & 3) * 4;
        qa0[0] = *(const uint32_t*)(Qp8 + (size_t)qr * HD + tg4);
        qa0[1] = *(const uint32_t*)(Qp8 + (size_t)(qr + 8) * HD + tg4);
        qa0[2] = *(const uint32_t*)(Qp8 + (size_t)qr * HD + tg4 + 16);
        qa0[3] = *(const uint32_t*)(Qp8 + (size_t)(qr + 8) * HD + tg4 + 16);
        qa1[0] = *(const uint32_t*)(Qp8 + (size_t)qr * HD + tg4 + 32);
        qa1[1] = *(const uint32_t*)(Qp8 + (size_t)(qr + 8) * HD + tg4 + 32);
        qa1[2] = *(const uint32_t*)(Qp8 + (size_t)qr * HD + tg4 + 48);
        qa1[3] = *(const uint32_t*)(Qp8 + (size_t)(qr + 8) * HD + tg4 + 48);
    }

    // fixed reference point m = 0 (arg = s*qs2, |arg|max ~ 8.5 << 127: safe)
    float l0 = 0.0f, l1 = 0.0f;

    // ================= PASS 1: row sumexp (triple-buffered K) =================
    PFK(0, 0); CPC();
    for (int t = 0; t < NT; t++) {
        if (t + 1 < NT) PFK(t + 1, (t + 1) % 3);
        CPC(); CPW1();
        __syncthreads();   // single barrier per iter: buf t%3 safe (last read t-2)
        const char* kptr = smc + (t % 3) * KB8;
#pragma unroll
        for (int qi = 0; qi < 4; qi++) {
            const int q = wodd ? (3 - qi) : qi;
            float sc[4][4];
            QKBLK(sc, kptr, q);
            SUMBLK(sc);
        }
    }

    // sum across the 4 lanes of each row group
    l0 += __shfl_xor_sync(0xffffffffu, l0, 1);
    l0 += __shfl_xor_sync(0xffffffffu, l0, 2);
    l1 += __shfl_xor_sync(0xffffffffu, l1, 1);
    l1 += __shfl_xor_sync(0xffffffffu, l1, 2);
    // p/dsc = 2^(S*qs2 + C);  C = -log2(l*dsc)
    const float C0 = -__log2f(l0 * dsc);
    const float C1 = -__log2f(l1 * dsc);

    float oacc[8][4];
#pragma unroll
    for (int i = 0; i < 8; i++)
#pragma unroll
        for (int j = 0; j < 4; j++) oacc[i][j] = 0.0f;

    __syncthreads();   // all pass-1 reads of K buf 0 done before pass-2 overwrites it

    // ================= PASS 2: quantized probs + PV (triple-buffered) =================
    PFK(0, 0); PFV(0, 0); CPC();
    for (int t = 0; t < NT; t++) {
        if (t + 1 < NT) { PFK(t + 1, (t + 1) % 3); PFV(t + 1, (t + 1) % 3); }
        CPC(); CPW1();
        __syncthreads();
        const char* kptr = smc + (t % 3) * KB8;
        const uint32_t vbuf = sb + 3 * KB8 + (uint32_t)(t % 3) * VBYTES;
#pragma unroll
        for (int qi = 0; qi < 4; qi++) {
            const int q = wodd ? (3 - qi) : qi;
            float sc[4][4];
            QKBLK(sc, kptr, q);
            PVQ(sc, q);
        }
    }

    // ---- epilogue: fp8 round-trip of O (hardware cvt), fp32 store ----
    const float pvi = dsc * svv / osc;
    float* Ob = out + ((size_t)h * SQ + s0 + w * 16) * HD;
#pragma unroll
    for (int dt = 0; dt < 8; dt++) {
        uint32_t h0 = q8pair(oacc[dt][0] * pvi, oacc[dt][1] * pvi);
        uint32_t h1 = q8pair(oacc[dt][2] * pvi, oacc[dt][3] * pvi);
        __half2 hh0 = *reinterpret_cast<const __half2*>(&h0);
        __half2 hh1 = *reinterpret_cast<const __half2*>(&h1);
        float2 f0 = __half22float2(hh0);
        float2 f1 = __half22float2(hh1);
        float2 r0v = make_float2(f0.x * osc, f0.y * osc);
        float2 r1v = make_float2(f1.x * osc, f1.y * osc);
        *(float2*)(Ob + (size_t)qr * HD + dt * 8 + qc * 2) = r0v;
        *(float2*)(Ob + (size_t)(qr + 8) * HD + dt * 8 + qc * 2) = r1v;
    }
}

extern "C" void kernel_launch(void* const* d_in, const int* in_sizes, int n_in,
                              void* d_out, int out_size) {
    const float* q = (const float*)d_in[0];
    const float* k = (const float*)d_in[1];
    const float* v = (const float*)d_in[2];
    const float* scale_q = (const float*)d_in[3];
    const float* scale_k = (const float*)d_in[4];
    const float* scale_v = (const float*)d_in[5];
    const float* descale_amax = (const float*)d_in[6];
    const float* out_scale = (const float*)d_in[7];
    float* out = (float*)d_out;

    void *qp, *kp;
    cudaGetSymbolAddress(&qp, g_q8b);
    cudaGetSymbolAddress(&kp, g_k8b);

    const int n4 = NH * SQ * HD / 4;
    quant8<<<dim3(n4 / 256, 1, 2), 256>>>((const float4*)q, (const float4*)k,
                                          (uint32_t*)qp, (uint32_t*)kp,
                                          scale_q, scale_k, n4);
    vtrans<<<dim3(SQ / 64, NH), 256>>>(v, scale_v);

    cudaFuncSetAttribute(attn_kernel, cudaFuncAttributeMaxDynamicSharedMemorySize,
                         SMEM_TOT);
    attn_kernel<<<dim3(SQ / BM, NH), 256, SMEM_TOT>>>(scale_q, scale_k, scale_v,
                                                      descale_amax, out_scale, out);
}

// round 14
// speedup vs baseline: 1.0621x; 1.0621x over previous
#include <cuda_runtime.h>
#include <cuda_fp8.h>
#include <cuda_fp16.h>
#include <math_constants.h>
#include <cstdint>

#define SQ 4096
#define HD 64
#define NH 16
#define BM 128
#define BN 128
#define NT (SQ / BN)
#define KSTR8 80           // K smem row stride in BYTES (16B-aligned, conflict-free)
#define VSTR 136           // V smem row stride in halves (272B: ldmatrix conflict-free)
#define KB8 (BN * KSTR8)         // 10240
#define VBYTES (HD * VSTR * 2)   // 17408
#define SMEM_TOT (3 * KB8 + 3 * VBYTES)  // 82944 (x2 CTAs = 166KB)

// Q/K as raw e4m3 codes (1 byte); V codes held exactly in fp16 (PV stays fp16 MMA)
__device__ uint8_t g_q8b[NH * SQ * HD];
__device__ uint8_t g_k8b[NH * SQ * HD];
__device__ __half  g_v8t[NH * HD * SQ];   // transposed [h][d][s]

// ---------- helpers ----------
__device__ __forceinline__ uint32_t s2u(const void* p) {
    uint32_t a;
    asm("{ .reg .u64 t; cvta.to.shared.u64 t, %1; cvt.u32.u64 %0, t; }"
        : "=r"(a) : "l"(p));
    return a;
}
__device__ __forceinline__ void cpa16(uint32_t dst, const void* src) {
    asm volatile("cp.async.cg.shared.global [%0], [%1], 16;" :: "r"(dst), "l"(src));
}
#define CPC() asm volatile("cp.async.commit_group;" ::: "memory")
#define CPW1() asm volatile("cp.async.wait_group 1;" ::: "memory")

// fp16 m16n8k16 (PV)
__device__ __forceinline__ void mma16816(float* c, const uint32_t* a,
                                         uint32_t b0, uint32_t b1) {
    asm volatile(
        "mma.sync.aligned.m16n8k16.row.col.f32.f16.f16.f32 "
        "{%0,%1,%2,%3}, {%4,%5,%6,%7}, {%8,%9}, {%0,%1,%2,%3};"
        : "+f"(c[0]), "+f"(c[1]), "+f"(c[2]), "+f"(c[3])
        : "r"(a[0]), "r"(a[1]), "r"(a[2]), "r"(a[3]), "r"(b0), "r"(b1));
}
// fp8 m16n8k32 (QK): A/B are raw e4m3 codes, fp32 accumulate (exact products)
__device__ __forceinline__ void mma8(float* c, const uint32_t* a,
                                     uint32_t b0, uint32_t b1) {
    asm volatile(
        "mma.sync.aligned.m16n8k32.row.col.f32.e4m3.e4m3.f32 "
        "{%0,%1,%2,%3}, {%4,%5,%6,%7}, {%8,%9}, {%0,%1,%2,%3};"
        : "+f"(c[0]), "+f"(c[1]), "+f"(c[2]), "+f"(c[3])
        : "r"(a[0]), "r"(a[1]), "r"(a[2]), "r"(a[3]), "r"(b0), "r"(b1));
}
__device__ __forceinline__ void ldm4(uint32_t* r, uint32_t addr) {
    asm volatile("ldmatrix.sync.aligned.m8n8.x4.shared.b16 {%0,%1,%2,%3}, [%4];"
                 : "=r"(r[0]), "=r"(r[1]), "=r"(r[2]), "=r"(r[3]) : "r"(addr));
}

// MUFU exp2 — same accuracy class (~2.4e-7) as the __expf that passed in R0
__device__ __forceinline__ float exp2p(float t) {
    float r;
    asm("ex2.approx.f32 %0, %1;" : "=f"(r) : "f"(t));
    return r;
}

// pair of floats -> e4m3 codes (satfinite RN-even) packed in 16 bits
__device__ __forceinline__ uint16_t c8pair(float x, float y) {
    return (uint16_t)__nv_cvt_float2_to_fp8x2(make_float2(x, y),
                                              __NV_SATFINITE, __NV_E4M3);
}
// pair of floats -> e4m3 grid -> fp16 pair (exact) for the PV fp16 path
__device__ __forceinline__ uint32_t q8pair(float x, float y) {
    __nv_fp8x2_storage_t b2 = __nv_cvt_float2_to_fp8x2(make_float2(x, y),
                                                       __NV_SATFINITE, __NV_E4M3);
    __half2_raw h2 = __nv_cvt_fp8x2_to_halfraw2(b2, __NV_E4M3);
    return *reinterpret_cast<const uint32_t*>(&h2);
}

// ---------- preprocessing: fp32 -> e4m3 code bytes ----------
// grid.z selects (input, scale): 0 -> q, 1 -> k
__global__ void quant8(const float4* __restrict__ qin, const float4* __restrict__ kin,
                       uint32_t* __restrict__ qout, uint32_t* __restrict__ kout,
                       const float* __restrict__ sq_p, const float* __restrict__ sk_p,
                       int n4) {
    int i = blockIdx.x * blockDim.x + threadIdx.x;
    if (i >= n4) return;
    const float4* in = blockIdx.z ? kin : qin;
    uint32_t* outp = blockIdx.z ? kout : qout;
    float inv = 1.0f / (blockIdx.z ? *sk_p : *sq_p);
    float4 v = in[i];
    uint32_t lo = c8pair(v.x * inv, v.y * inv);
    uint32_t hi = c8pair(v.z * inv, v.w * inv);
    outp[i] = lo | (hi << 16);
}

__global__ void vtrans(const float* __restrict__ v, const float* __restrict__ sp) {
    __shared__ __half t[64][66];
    int h = blockIdx.y, st = blockIdx.x * 64;
    float inv = 1.0f / *sp;
    int tid = threadIdx.x;
#pragma unroll
    for (int e = 0; e < 16; e++) {
        int lin = tid + e * 256;
        int sr = lin >> 6, d = lin & 63;
        uint32_t pr = q8pair(v[((size_t)h * SQ + st + sr) * HD + d] * inv, 0.0f);
        t[sr][d] = *reinterpret_cast<const __half*>(&pr);
    }
    __syncthreads();
#pragma unroll
    for (int e = 0; e < 16; e++) {
        int lin = tid + e * 256;
        int d = lin >> 6, sc = lin & 63;
        g_v8t[((size_t)h * HD + d) * SQ + st + sc] = t[sc][d];
    }
}

// ---- shared macros ----
// K tile prefetch: 128 rows x 64 code bytes, smem stride 80
#define PFK(t, b) do {                                                        \
        const uint8_t* src = Kp8 + (size_t)(t) * BN * HD;                     \
        uint32_t db = sb + (b) * KB8;                                         \
        _Pragma("unroll")                                                     \
        for (int i_ = 0; i_ < 2; i_++) {                                      \
            int idx = tid + i_ * 256; int row = idx >> 2, seg = idx & 3;      \
            cpa16(db + row * KSTR8 + seg * 16, src + row * HD + seg * 16);    \
        } } while (0)
#define PFV(t, b) do {                                                        \
        uint32_t db = sb + 3 * KB8 + (b) * VBYTES;                            \
        _Pragma("unroll")                                                     \
        for (int i_ = 0; i_ < 4; i_++) {                                      \
            int idx = tid + i_ * 256; int d = idx >> 4, seg = idx & 15;       \
            cpa16(db + d * (VSTR * 2) + seg * 16,                             \
                  Vp + (size_t)d * SQ + (t) * BN + seg * 8);                  \
        } } while (0)
// QK score block: 16 rows x 32 keys via fp8 m16n8k32, ldmatrix-fed B.
// One ldmatrix.x4 delivers the 4 k-chunk fragments of an 8-key tile.
#define QKBLK(sc, kbuf, q) do {                                               \
        _Pragma("unroll")                                                     \
        for (int jj_ = 0; jj_ < 4; jj_++) {                                   \
            sc[jj_][0] = sc[jj_][1] = sc[jj_][2] = sc[jj_][3] = 0.0f;         \
            uint32_t ad_ = (kbuf) + kq8m_lane +                               \
                           (uint32_t)(((q) * 32 + jj_ * 8) * KSTR8);          \
            uint32_t f_[4];                                                   \
            ldm4(f_, ad_);                                                    \
            mma8(sc[jj_], qa0, f_[0], f_[1]);                                 \
            mma8(sc[jj_], qa1, f_[2], f_[3]);                                 \
        } } while (0)
// pass-1 per-q work: accumulate sumexp from a score block
#define SUMBLK(sc) do {                                                       \
        float a0_ = 0.0f, a1_ = 0.0f;                                         \
        _Pragma("unroll")                                                     \
        for (int jj_ = 0; jj_ < 4; jj_++) {                                   \
            a0_ += exp2p(sc[jj_][0] * qs2) + exp2p(sc[jj_][1] * qs2);         \
            a1_ += exp2p(sc[jj_][2] * qs2) + exp2p(sc[jj_][3] * qs2);         \
        }                                                                     \
        l0 += a0_;                                                            \
        l1 += a1_;                                                            \
    } while (0)
// pass-2 per-q work: quantize probs (fp16 frags) + PV fp16 MMAs, V ldm early
#define PVQ(sc, q) do {                                                       \
        uint32_t gA_[4], gB_[4];                                              \
        uint32_t avb_ = vbuf + v_lane + (uint32_t)((q) * 64);                 \
        ldm4(gA_, avb_);                                                      \
        uint32_t pa[2][4];                                                    \
        _Pragma("unroll")                                                     \
        for (int c_ = 0; c_ < 2; c_++) {                                      \
            _Pragma("unroll")                                                 \
            for (int hf_ = 0; hf_ < 2; hf_++) {                               \
                const float* s4_ = sc[2 * c_ + hf_];                          \
                float e00_ = exp2p(fmaf(s4_[0], qs2, C0));                    \
                float e01_ = exp2p(fmaf(s4_[1], qs2, C0));                    \
                float e10_ = exp2p(fmaf(s4_[2], qs2, C1));                    \
                float e11_ = exp2p(fmaf(s4_[3], qs2, C1));                    \
                pa[c_][2 * hf_ + 0] = q8pair(e00_, e01_);                     \
                pa[c_][2 * hf_ + 1] = q8pair(e10_, e11_);                     \
            }                                                                 \
        }                                                                     \
        _Pragma("unroll")                                                     \
        for (int dt_ = 0; dt_ < 8; dt_++) {                                   \
            uint32_t* gc_ = (dt_ & 1) ? gB_ : gA_;                            \
            uint32_t* gn_ = (dt_ & 1) ? gA_ : gB_;                            \
            if (dt_ < 7)                                                      \
                ldm4(gn_, avb_ + (uint32_t)((dt_ + 1) * 8) * (VSTR * 2));     \
            mma16816(oacc[dt_], pa[0], gc_[0], gc_[1]);                       \
            mma16816(oacc[dt_], pa[1], gc_[2], gc_[3]);                       \
        } } while (0)

// ---------- fused attention: pass 1 (sumexp) + pass 2 (quantized probs + PV) ----------
__global__ __launch_bounds__(256, 2) void attn_kernel(
    const float* __restrict__ sq_p, const float* __restrict__ sk_p,
    const float* __restrict__ sv_p, const float* __restrict__ dsc_p,
    const float* __restrict__ osc_p, float* __restrict__ out) {
    extern __shared__ char smc[];
    const uint32_t sb = s2u(smc);
    const int tid = threadIdx.x;
    const int w = tid >> 5, l = tid & 31;
    const int qr = l >> 2, qc = l & 3;
    const int h = blockIdx.y, s0 = blockIdx.x * BM;
    const int wodd = w & 1;   // odd warps sweep q-blocks in reverse (phase stagger)

    const float sqv = __ldg(sq_p), skv = __ldg(sk_p), svv = __ldg(sv_p);
    const float dsc = __ldg(dsc_p), osc = __ldg(osc_p);
    const float qs2 = sqv * skv * 0.125f * 1.4426950408889634f;

    // ldmatrix lane offsets: K fp8 (matrix = k-chunk, row = key), V fp16
    const uint32_t kq8m_lane = (uint32_t)(l & 7) * KSTR8 + (uint32_t)(l >> 3) * 16;
    const uint32_t v_lane = (uint32_t)(l & 7) * (VSTR * 2) + (uint32_t)(l >> 3) * 16;

    const uint8_t* Qp8 = g_q8b + ((size_t)h * SQ + s0 + w * 16) * HD;
    const uint8_t* Kp8 = g_k8b + (size_t)h * SQ * HD;
    const __half* Vp = g_v8t + (size_t)h * HD * SQ;

    // Q fp8 A-fragments: 16 rows x 64 d per warp = 2 k32-chunks x 4 regs
    uint32_t qa0[4], qa1[4];
    {
        const int tg4 = (l & 3) * 4;
        qa0[0] = *(const uint32_t*)(Qp8 + (size_t)qr * HD + tg4);
        qa0[1] = *(const uint32_t*)(Qp8 + (size_t)(qr + 8) * HD + tg4);
        qa0[2] = *(const uint32_t*)(Qp8 + (size_t)qr * HD + tg4 + 16);
        qa0[3] = *(const uint32_t*)(Qp8 + (size_t)(qr + 8) * HD + tg4 + 16);
        qa1[0] = *(const uint32_t*)(Qp8 + (size_t)qr * HD + tg4 + 32);
        qa1[1] = *(const uint32_t*)(Qp8 + (size_t)(qr + 8) * HD + tg4 + 32);
        qa1[2] = *(const uint32_t*)(Qp8 + (size_t)qr * HD + tg4 + 48);
        qa1[3] = *(const uint32_t*)(Qp8 + (size_t)(qr + 8) * HD + tg4 + 48);
    }

    // fixed reference point m = 0 (arg = s*qs2, |arg|max ~ 8.5 << 127: safe)
    float l0 = 0.0f, l1 = 0.0f;

    // ================= PASS 1: row sumexp (triple-buffered K) =================
    PFK(0, 0); CPC();
    for (int t = 0; t < NT; t++) {
        if (t + 1 < NT) PFK(t + 1, (t + 1) % 3);
        CPC(); CPW1();
        __syncthreads();   // single barrier per iter: buf t%3 safe (last read t-2)
        const uint32_t kbuf = sb + (uint32_t)(t % 3) * KB8;
#pragma unroll
        for (int qi = 0; qi < 4; qi++) {
            const int q = wodd ? (3 - qi) : qi;
            float sc[4][4];
            QKBLK(sc, kbuf, q);
            SUMBLK(sc);
        }
    }

    // sum across the 4 lanes of each row group
    l0 += __shfl_xor_sync(0xffffffffu, l0, 1);
    l0 += __shfl_xor_sync(0xffffffffu, l0, 2);
    l1 += __shfl_xor_sync(0xffffffffu, l1, 1);
    l1 += __shfl_xor_sync(0xffffffffu, l1, 2);
    // p/dsc = 2^(S*qs2 + C);  C = -log2(l*dsc)
    const float C0 = -__log2f(l0 * dsc);
    const float C1 = -__log2f(l1 * dsc);

    float oacc[8][4];
#pragma unroll
    for (int i = 0; i < 8; i++)
#pragma unroll
        for (int j = 0; j < 4; j++) oacc[i][j] = 0.0f;

    __syncthreads();   // all pass-1 reads of K buf 0 done before pass-2 overwrites it

    // ================= PASS 2: quantized probs + PV (triple-buffered) =================
    PFK(0, 0); PFV(0, 0); CPC();
    for (int t = 0; t < NT; t++) {
        if (t + 1 < NT) { PFK(t + 1, (t + 1) % 3); PFV(t + 1, (t + 1) % 3); }
        CPC(); CPW1();
        __syncthreads();
        const uint32_t kbuf = sb + (uint32_t)(t % 3) * KB8;
        const uint32_t vbuf = sb + 3 * KB8 + (uint32_t)(t % 3) * VBYTES;
#pragma unroll
        for (int qi = 0; qi < 4; qi++) {
            const int q = wodd ? (3 - qi) : qi;
            float sc[4][4];
            QKBLK(sc, kbuf, q);
            PVQ(sc, q);
        }
    }

    // ---- epilogue: fp8 round-trip of O (hardware cvt), fp32 store ----
    const float pvi = dsc * svv / osc;
    float* Ob = out + ((size_t)h * SQ + s0 + w * 16) * HD;
#pragma unroll
    for (int dt = 0; dt < 8; dt++) {
        uint32_t h0 = q8pair(oacc[dt][0] * pvi, oacc[dt][1] * pvi);
        uint32_t h1 = q8pair(oacc[dt][2] * pvi, oacc[dt][3] * pvi);
        __half2 hh0 = *reinterpret_cast<const __half2*>(&h0);
        __half2 hh1 = *reinterpret_cast<const __half2*>(&h1);
        float2 f0 = __half22float2(hh0);
        float2 f1 = __half22float2(hh1);
        float2 r0v = make_float2(f0.x * osc, f0.y * osc);
        float2 r1v = make_float2(f1.x * osc, f1.y * osc);
        *(float2*)(Ob + (size_t)qr * HD + dt * 8 + qc * 2) = r0v;
        *(float2*)(Ob + (size_t)(qr + 8) * HD + dt * 8 + qc * 2) = r1v;
    }
}

extern "C" void kernel_launch(void* const* d_in, const int* in_sizes, int n_in,
                              void* d_out, int out_size) {
    const float* q = (const float*)d_in[0];
    const float* k = (const float*)d_in[1];
    const float* v = (const float*)d_in[2];
    const float* scale_q = (const float*)d_in[3];
    const float* scale_k = (const float*)d_in[4];
    const float* scale_v = (const float*)d_in[5];
    const float* descale_amax = (const float*)d_in[6];
    const float* out_scale = (const float*)d_in[7];
    float* out = (float*)d_out;

    void *qp, *kp;
    cudaGetSymbolAddress(&qp, g_q8b);
    cudaGetSymbolAddress(&kp, g_k8b);

    const int n4 = NH * SQ * HD / 4;
    quant8<<<dim3(n4 / 256, 1, 2), 256>>>((const float4*)q, (const float4*)k,
                                          (uint32_t*)qp, (uint32_t*)kp,
                                          scale_q, scale_k, n4);
    vtrans<<<dim3(SQ / 64, NH), 256>>>(v, scale_v);

    cudaFuncSetAttribute(attn_kernel, cudaFuncAttributeMaxDynamicSharedMemorySize,
                         SMEM_TOT);
    attn_kernel<<<dim3(SQ / BM, NH), 256, SMEM_TOT>>>(scale_q, scale_k, scale_v,
                                                      descale_amax, out_scale, out);
}

// round 15
// speedup vs baseline: 1.1608x; 1.0929x over previous
#include <cuda_runtime.h>
#include <cuda_fp8.h>
#include <cuda_fp16.h>
#include <math_constants.h>
#include <cstdint>

#define SQ 4096
#define HD 64
#define NH 16
#define BM 128
#define BN 128
#define NT (SQ / BN)
#define KSTR 72            // K smem row stride in halves (144B: ldmatrix conflict-free)
#define VSTR 136           // V smem row stride in halves (272B: ldmatrix conflict-free)
#define KBYTES (BN * KSTR * 2)   // 18432
#define VBYTES (HD * VSTR * 2)   // 17408
#define SMEM_TOT (3 * KBYTES + 3 * VBYTES)  // 107520 (x2 CTAs = 215KB <= 228KB)

// raw e4m3 code values held exactly in fp16
__device__ __half g_q8[NH * SQ * HD];
__device__ __half g_k8[NH * SQ * HD];
__device__ __half g_v8t[NH * HD * SQ];   // transposed [h][d][s]

// ---------- helpers ----------
__device__ __forceinline__ uint32_t s2u(const void* p) {
    uint32_t a;
    asm("{ .reg .u64 t; cvta.to.shared.u64 t, %1; cvt.u32.u64 %0, t; }"
        : "=r"(a) : "l"(p));
    return a;
}
__device__ __forceinline__ void cpa16(uint32_t dst, const void* src) {
    asm volatile("cp.async.cg.shared.global [%0], [%1], 16;" :: "r"(dst), "l"(src));
}
#define CPC() asm volatile("cp.async.commit_group;" ::: "memory")
#define CPW1() asm volatile("cp.async.wait_group 1;" ::: "memory")

__device__ __forceinline__ void mma16816(float* c, const uint32_t* a,
                                         uint32_t b0, uint32_t b1) {
    asm volatile(
        "mma.sync.aligned.m16n8k16.row.col.f32.f16.f16.f32 "
        "{%0,%1,%2,%3}, {%4,%5,%6,%7}, {%8,%9}, {%0,%1,%2,%3};"
        : "+f"(c[0]), "+f"(c[1]), "+f"(c[2]), "+f"(c[3])
        : "r"(a[0]), "r"(a[1]), "r"(a[2]), "r"(a[3]), "r"(b0), "r"(b1));
}
__device__ __forceinline__ void ldm4(uint32_t* r, uint32_t addr) {
    asm volatile("ldmatrix.sync.aligned.m8n8.x4.shared.b16 {%0,%1,%2,%3}, [%4];"
                 : "=r"(r[0]), "=r"(r[1]), "=r"(r[2]), "=r"(r[3]) : "r"(addr));
}

// MUFU exp2 — same accuracy class (~2.4e-7) as the __expf that passed in R0
__device__ __forceinline__ float exp2p(float t) {
    float r;
    asm("ex2.approx.f32 %0, %1;" : "=f"(r) : "f"(t));
    return r;
}

// pair of floats -> e4m3 (satfinite RN-even, hardware) -> fp16 pair (exact)
__device__ __forceinline__ uint32_t q8pair(float x, float y) {
    __nv_fp8x2_storage_t b2 = __nv_cvt_float2_to_fp8x2(make_float2(x, y),
                                                       __NV_SATFINITE, __NV_E4M3);
    __half2_raw h2 = __nv_cvt_fp8x2_to_halfraw2(b2, __NV_E4M3);
    return *reinterpret_cast<const uint32_t*>(&h2);
}

// ---------- fused preprocessing: fp32 -> e4m3 codes in fp16 ----------
// grid.z: 0 -> quantize Q, 1 -> quantize K, 2 -> quantize+transpose V
__global__ void prep(const float4* __restrict__ qin, const float4* __restrict__ kin,
                     const float* __restrict__ vin,
                     uint32_t* __restrict__ qout, uint32_t* __restrict__ kout,
                     const float* __restrict__ sq_p, const float* __restrict__ sk_p,
                     const float* __restrict__ sv_p, int n4) {
    __shared__ __half t[64][66];
    if (blockIdx.z < 2) {
        int i = blockIdx.x * blockDim.x + threadIdx.x;
        if (i >= n4) return;
        const float4* in = blockIdx.z ? kin : qin;
        uint32_t* outp = blockIdx.z ? kout : qout;
        float inv = 1.0f / (blockIdx.z ? *sk_p : *sq_p);
        float4 v = in[i];
        outp[2 * i]     = q8pair(v.x * inv, v.y * inv);
        outp[2 * i + 1] = q8pair(v.z * inv, v.w * inv);
        return;
    }
    // V path: 1024 active blocks (x < 1024), 64-row transpose tiles
    if (blockIdx.x >= (SQ / 64) * NH) return;
    int h = blockIdx.x & (NH - 1), st = (blockIdx.x >> 4) * 64;
    float inv = 1.0f / *sv_p;
    int tid = threadIdx.x;
#pragma unroll
    for (int e = 0; e < 16; e++) {
        int lin = tid + e * 256;
        int sr = lin >> 6, d = lin & 63;
        uint32_t pr = q8pair(vin[((size_t)h * SQ + st + sr) * HD + d] * inv, 0.0f);
        t[sr][d] = *reinterpret_cast<const __half*>(&pr);
    }
    __syncthreads();
#pragma unroll
    for (int e = 0; e < 16; e++) {
        int lin = tid + e * 256;
        int d = lin >> 6, sc = lin & 63;
        g_v8t[((size_t)h * HD + d) * SQ + st + sc] = t[sc][d];
    }
}

// ---- shared macros ----
#define PFK(t, b) do {                                                        \
        const __half* src = Kp + (size_t)(t) * BN * HD;                       \
        uint32_t db = sb + (b) * KBYTES;                                      \
        _Pragma("unroll")                                                     \
        for (int i_ = 0; i_ < 4; i_++) {                                      \
            int idx = tid + i_ * 256; int row = idx >> 3, seg = idx & 7;      \
            cpa16(db + row * (KSTR * 2) + seg * 16, src + row * HD + seg * 8);\
        } } while (0)
#define PFV(t, b) do {                                                        \
        uint32_t db = sb + 3 * KBYTES + (b) * VBYTES;                         \
        _Pragma("unroll")                                                     \
        for (int i_ = 0; i_ < 4; i_++) {                                      \
            int idx = tid + i_ * 256; int d = idx >> 4, seg = idx & 15;       \
            cpa16(db + d * (VSTR * 2) + seg * 16,                             \
                  Vp + (size_t)d * SQ + (t) * BN + seg * 8);                  \
        } } while (0)
#define QKBLK(sc, kbuf, q) do {                                               \
        _Pragma("unroll")                                                     \
        for (int jj_ = 0; jj_ < 4; jj_++) {                                   \
            sc[jj_][0] = sc[jj_][1] = sc[jj_][2] = sc[jj_][3] = 0.0f;         \
            uint32_t ad_ = (kbuf) + kq_lane +                                 \
                           (uint32_t)(((q) * 4 + jj_) * 8) * (KSTR * 2);      \
            uint32_t f0_[4], f1_[4];                                          \
            ldm4(f0_, ad_); ldm4(f1_, ad_ + 64);                              \
            mma16816(sc[jj_], qa[0], f0_[0], f0_[1]);                         \
            mma16816(sc[jj_], qa[1], f0_[2], f0_[3]);                         \
            mma16816(sc[jj_], qa[2], f1_[0], f1_[1]);                         \
            mma16816(sc[jj_], qa[3], f1_[2], f1_[3]);                         \
        } } while (0)
#define SUMBLK(sc) do {                                                       \
        float a0_ = 0.0f, a1_ = 0.0f;                                         \
        _Pragma("unroll")                                                     \
        for (int jj_ = 0; jj_ < 4; jj_++) {                                   \
            a0_ += exp2p(sc[jj_][0] * qs2) + exp2p(sc[jj_][1] * qs2);         \
            a1_ += exp2p(sc[jj_][2] * qs2) + exp2p(sc[jj_][3] * qs2);         \
        }                                                                     \
        l0 += a0_;                                                            \
        l1 += a1_;                                                            \
    } while (0)
#define PVQ(sc, q) do {                                                       \
        uint32_t pa[2][4];                                                    \
        _Pragma("unroll")                                                     \
        for (int c_ = 0; c_ < 2; c_++) {                                      \
            _Pragma("unroll")                                                 \
            for (int hf_ = 0; hf_ < 2; hf_++) {                               \
                const float* s4_ = sc[2 * c_ + hf_];                          \
                float e00_ = exp2p(fmaf(s4_[0], qs2, C0));                    \
                float e01_ = exp2p(fmaf(s4_[1], qs2, C0));                    \
                float e10_ = exp2p(fmaf(s4_[2], qs2, C1));                    \
                float e11_ = exp2p(fmaf(s4_[3], qs2, C1));                    \
                pa[c_][2 * hf_ + 0] = q8pair(e00_, e01_);                     \
                pa[c_][2 * hf_ + 1] = q8pair(e10_, e11_);                     \
            }                                                                 \
        }                                                                     \
        _Pragma("unroll")                                                     \
        for (int dt_ = 0; dt_ < 8; dt_++) {                                   \
            uint32_t av_ = vbuf + v_lane + (uint32_t)(dt_ * 8) * (VSTR * 2) + \
                           (uint32_t)((q) * 64);                              \
            uint32_t g_[4];                                                   \
            ldm4(g_, av_);                                                    \
            mma16816(oacc[dt_], pa[0], g_[0], g_[1]);                         \
            mma16816(oacc[dt_], pa[1], g_[2], g_[3]);                         \
        } } while (0)

// ---------- fused attention: pass 1 (sumexp) + pass 2 (quantized probs + PV) ----------
__global__ __launch_bounds__(256, 2) void attn_kernel(
    const float* __restrict__ sq_p, const float* __restrict__ sk_p,
    const float* __restrict__ sv_p, const float* __restrict__ dsc_p,
    const float* __restrict__ osc_p, float* __restrict__ out) {
    extern __shared__ char smc[];
    const uint32_t sb = s2u(smc);
    const int tid = threadIdx.x;
    const int w = tid >> 5, l = tid & 31;
    const int qr = l >> 2, qc = l & 3;
    const int h = blockIdx.y, s0 = blockIdx.x * BM;
    const int wodd = w & 1;   // odd warps sweep q-blocks in reverse (phase stagger)

    const float sqv = __ldg(sq_p), skv = __ldg(sk_p), svv = __ldg(sv_p);
    const float dsc = __ldg(dsc_p), osc = __ldg(osc_p);
    const float qs2 = sqv * skv * 0.125f * 1.4426950408889634f;

    // per-lane ldmatrix base offsets (matrix = l>>3, row-in-matrix = l&7)
    const uint32_t kq_lane = (uint32_t)(l & 7) * (KSTR * 2) + (uint32_t)(l >> 3) * 16;
    const uint32_t v_lane  = (uint32_t)(l & 7) * (VSTR * 2) + (uint32_t)(l >> 3) * 16;

    const __half* Qp = g_q8 + ((size_t)h * SQ + s0 + w * 16) * HD;
    const __half* Kp = g_k8 + (size_t)h * SQ * HD;
    const __half* Vp = g_v8t + (size_t)h * HD * SQ;

    // Q fragments: 16 rows x 64 cols per warp, resident in registers
    uint32_t qa[4][4];
#pragma unroll
    for (int kc = 0; kc < 4; kc++) {
        qa[kc][0] = *(const uint32_t*)(Qp + (size_t)qr * HD + kc * 16 + qc * 2);
        qa[kc][1] = *(const uint32_t*)(Qp + (size_t)(qr + 8) * HD + kc * 16 + qc * 2);
        qa[kc][2] = *(const uint32_t*)(Qp + (size_t)qr * HD + kc * 16 + 8 + qc * 2);
        qa[kc][3] = *(const uint32_t*)(Qp + (size_t)(qr + 8) * HD + kc * 16 + 8 + qc * 2);
    }

    // fixed reference point m = 0 (arg = s*qs2, |arg|max ~ 8.5 << 127: safe)
    float l0 = 0.0f, l1 = 0.0f;

    // ================= PASS 1: row sumexp (triple-buffered K) =================
    PFK(0, 0); CPC();
    for (int t = 0; t < NT; t++) {
        if (t + 1 < NT) PFK(t + 1, (t + 1) % 3);
        CPC(); CPW1();
        __syncthreads();   // single barrier per iter: buf t%3 safe (last read t-2)
        const uint32_t kbuf = sb + (uint32_t)(t % 3) * KBYTES;
#pragma unroll
        for (int qi = 0; qi < 4; qi++) {
            const int q = wodd ? (3 - qi) : qi;
            float sc[4][4];
            QKBLK(sc, kbuf, q);
            SUMBLK(sc);
        }
    }

    // sum across the 4 lanes of each row group
    l0 += __shfl_xor_sync(0xffffffffu, l0, 1);
    l0 += __shfl_xor_sync(0xffffffffu, l0, 2);
    l1 += __shfl_xor_sync(0xffffffffu, l1, 1);
    l1 += __shfl_xor_sync(0xffffffffu, l1, 2);
    // p/dsc = 2^(S*qs2 + C);  C = -log2(l*dsc)
    const float C0 = -__log2f(l0 * dsc);
    const float C1 = -__log2f(l1 * dsc);

    float oacc[8][4];
#pragma unroll
    for (int i = 0; i < 8; i++)
#pragma unroll
        for (int j = 0; j < 4; j++) oacc[i][j] = 0.0f;

    __syncthreads();   // all pass-1 reads of K buf 0 done before pass-2 overwrites it

    // ================= PASS 2: quantized probs + PV (triple-buffered) =================
    PFK(0, 0); PFV(0, 0); CPC();
    for (int t = 0; t < NT; t++) {
        if (t + 1 < NT) { PFK(t + 1, (t + 1) % 3); PFV(t + 1, (t + 1) % 3); }
        CPC(); CPW1();
        __syncthreads();
        const uint32_t kbuf = sb + (uint32_t)(t % 3) * KBYTES;
        const uint32_t vbuf = sb + 3 * KBYTES + (uint32_t)(t % 3) * VBYTES;
#pragma unroll
        for (int qi = 0; qi < 4; qi++) {
            const int q = wodd ? (3 - qi) : qi;
            float sc[4][4];
            QKBLK(sc, kbuf, q);
            PVQ(sc, q);
        }
    }

    // ---- epilogue: fp8 round-trip of O (hardware cvt), fp32 store ----
    const float pvi = dsc * svv / osc;
    float* Ob = out + ((size_t)h * SQ + s0 + w * 16) * HD;
#pragma unroll
    for (int dt = 0; dt < 8; dt++) {
        uint32_t h0 = q8pair(oacc[dt][0] * pvi, oacc[dt][1] * pvi);
        uint32_t h1 = q8pair(oacc[dt][2] * pvi, oacc[dt][3] * pvi);
        __half2 hh0 = *reinterpret_cast<const __half2*>(&h0);
        __half2 hh1 = *reinterpret_cast<const __half2*>(&h1);
        float2 f0 = __half22float2(hh0);
        float2 f1 = __half22float2(hh1);
        float2 r0v = make_float2(f0.x * osc, f0.y * osc);
        float2 r1v = make_float2(f1.x * osc, f1.y * osc);
        *(float2*)(Ob + (size_t)qr * HD + dt * 8 + qc * 2) = r0v;
        *(float2*)(Ob + (size_t)(qr + 8) * HD + dt * 8 + qc * 2) = r1v;
    }
}

extern "C" void kernel_launch(void* const* d_in, const int* in_sizes, int n_in,
                              void* d_out, int out_size) {
    const float* q = (const float*)d_in[0];
    const float* k = (const float*)d_in[1];
    const float* v = (const float*)d_in[2];
    const float* scale_q = (const float*)d_in[3];
    const float* scale_k = (const float*)d_in[4];
    const float* scale_v = (const float*)d_in[5];
    const float* descale_amax = (const float*)d_in[6];
    const float* out_scale = (const float*)d_in[7];
    float* out = (float*)d_out;

    void *qp, *kp;
    cudaGetSymbolAddress(&qp, g_q8);
    cudaGetSymbolAddress(&kp, g_k8);

    const int n4 = NH * SQ * HD / 4;
    prep<<<dim3(n4 / 256, 1, 3), 256>>>((const float4*)q, (const float4*)k, v,
                                        (uint32_t*)qp, (uint32_t*)kp,
                                        scale_q, scale_k, scale_v, n4);

    cudaFuncSetAttribute(attn_kernel, cudaFuncAttributeMaxDynamicSharedMemorySize,
                         SMEM_TOT);
    attn_kernel<<<dim3(SQ / BM, NH), 256, SMEM_TOT>>>(scale_q, scale_k, scale_v,
                                                      descale_amax, out_scale, out);
}